// round 10
// baseline (speedup 1.0000x reference)
#include <cuda_runtime.h>
#include <math.h>

#define NN   6000
#define EE   192000
#define DIN  512
#define HH   128
#define NPB  8           // nodes per block in p-kernel
#define EOSF 1e-10f

// Scratch (__device__ globals allowed; heap allocs are not).
__device__ int   g_win[(size_t)NN * NN];   // winner edge-index+1 per cell (only edge cells touched)
__device__ float g_p[NN];
__device__ float g_dlp[NN];
__device__ float g_dhp[NN];
__device__ float g_ilp[NN];
__device__ float g_ihp[NN];
__device__ float g_vlp[EE];                // precomputed adj_lp value per edge (0 = not winner)
__device__ float g_vhp[EE];                // precomputed adj_hp value per edge

// SM-side zero fill (write-through float4 stores — best measured variant).
__global__ void __launch_bounds__(512) k_fill(float4* __restrict__ dst, size_t n4) {
    size_t i = (size_t)blockIdx.x * blockDim.x + threadIdx.x;
    size_t stride = (size_t)gridDim.x * blockDim.x;
    const float4 z = make_float4(0.f, 0.f, 0.f, 0.f);
    for (; i < n4; i += stride) __stwt(dst + i, z);
}

// Clear winner at all edge cells; init degrees to 1.0 (the +eye term in row sums).
__global__ void k_clear(const int* __restrict__ edges) {
    int t = blockIdx.x * blockDim.x + threadIdx.x;
    if (t < EE) {
        int u = edges[t], v = edges[EE + t];
        g_win[u * NN + v] = 0;
    }
    if (t < NN) { g_dlp[t] = 1.0f; g_dhp[t] = 1.0f; }
}

// Last-edge-wins dedup: winner = max edge index + 1.
__global__ void k_max(const int* __restrict__ edges) {
    int e = blockIdx.x * blockDim.x + threadIdx.x;
    if (e >= EE) return;
    int u = edges[e], v = edges[EE + e];
    atomicMax(&g_win[u * NN + v], e + 1);
}

// p[n] = sum_h relu(feat[n]·w_emb[:,h] + b_emb[h]) * (w_mlp[h] + w_mlp[H+h])
__global__ void __launch_bounds__(HH) k_p(const float* __restrict__ feat,
                                          const float* __restrict__ wemb,
                                          const float* __restrict__ bemb,
                                          const float* __restrict__ wmlp) {
    __shared__ float sf[NPB][DIN];
    int h  = threadIdx.x;
    int n0 = blockIdx.x * NPB;

    const float4* f4 = (const float4*)(feat + (size_t)n0 * DIN);
    float4* s4 = (float4*)&sf[0][0];
    const int total4 = NPB * DIN / 4;
    for (int i = h; i < total4; i += HH) s4[i] = f4[i];
    __syncthreads();

    float acc[NPB];
#pragma unroll
    for (int j = 0; j < NPB; j++) acc[j] = 0.0f;

    for (int d = 0; d < DIN; d += 4) {
        float w0 = wemb[(d + 0) * HH + h];
        float w1 = wemb[(d + 1) * HH + h];
        float w2 = wemb[(d + 2) * HH + h];
        float w3 = wemb[(d + 3) * HH + h];
#pragma unroll
        for (int j = 0; j < NPB; j++) {
            float4 f = *(const float4*)&sf[j][d];
            acc[j] = fmaf(f.x, w0, acc[j]);
            acc[j] = fmaf(f.y, w1, acc[j]);
            acc[j] = fmaf(f.z, w2, acc[j]);
            acc[j] = fmaf(f.w, w3, acc[j]);
        }
    }

    float b  = bemb[h];
    float ws = wmlp[h] + wmlp[HH + h];
    __shared__ float red[4][NPB];
#pragma unroll
    for (int j = 0; j < NPB; j++) {
        float v = acc[j] + b;
        v = (v > 0.0f) ? v * ws : 0.0f;
#pragma unroll
        for (int off = 16; off; off >>= 1) v += __shfl_down_sync(0xffffffffu, v, off);
        if ((h & 31) == 0) red[h >> 5][j] = v;
    }
    __syncthreads();
    if (h < NPB)
        g_p[n0 + h] = red[0][h] + red[1][h] + red[2][h] + red[3][h];
}

// Per-edge gating weights + winner-only degree accumulation (row sums).
__global__ void k_edge(const int* __restrict__ edges, const float* __restrict__ gn,
                       const float* __restrict__ bmlp,
                       float* __restrict__ wlp_out, float* __restrict__ whp_out) {
    int e = blockIdx.x * blockDim.x + threadIdx.x;
    if (e >= EE) return;
    int u = edges[e], v = edges[EE + e];
    float raw = 0.5f * (g_p[u] + g_p[v]) + bmlp[0];
    float x   = gn[e] + raw;               // TEMP = 1
    float wlp = 1.0f / (1.0f + expf(-x));
    wlp_out[e] = wlp;
    whp_out[e] = 1.0f - wlp;
    if (g_win[u * NN + v] == e + 1) {       // deduped adjacency contribution
        atomicAdd(&g_dlp[u], wlp);
        atomicAdd(&g_dhp[u], 1.0f - wlp);
    }
}

__global__ void k_inv() {
    int i = blockIdx.x * blockDim.x + threadIdx.x;
    if (i >= NN) return;
    g_ilp[i] = 1.0f / (sqrtf(g_dlp[i]) + EOSF);
    g_ihp[i] = 1.0f / (sqrtf(g_dhp[i]) + EOSF);
}

// Precompute per-edge scatter values (hidden under the fill window).
// val_lp == 0 marks non-winner edges (winners always have val_lp > 0).
__global__ void k_vals(const int* __restrict__ edges, const float* __restrict__ wlp_out) {
    int e = blockIdx.x * blockDim.x + threadIdx.x;
    if (e >= EE) return;
    int u = edges[e], v = edges[EE + e];
    size_t cell = (size_t)u * NN + v;
    float vlp = 0.0f, vhp = 0.0f;
    if (g_win[cell] == e + 1) {
        float wlp = wlp_out[e];
        float il = g_ilp[u] * g_ilp[v];
        float ih = g_ihp[u] * g_ihp[v];
        if (u == v) {
            vlp = (1.0f + wlp) * il;             // eye + self-edge, normalized
            vhp = 1.0f - (2.0f - wlp) * ih;      // 1 - (whp + 1)*ih
        } else {
            vlp = wlp * il;
            vhp = -(1.0f - wlp) * ih;
        }
    }
    g_vlp[e] = vlp;
    g_vhp[e] = vhp;
}

// Lean adjacency scatter: coalesced loads + 2 random stores per winner edge,
// plus the diagonal base values.
__global__ void k_fin_adj(const int* __restrict__ edges,
                          float* __restrict__ adj_lp, float* __restrict__ adj_hp) {
    int t = blockIdx.x * blockDim.x + threadIdx.x;
    if (t < EE) {
        float vlp = g_vlp[t];
        if (vlp == 0.0f) return;
        int u = edges[t], v = edges[EE + t];
        size_t cell = (size_t)u * NN + v;
        adj_lp[cell] = vlp;
        adj_hp[cell] = g_vhp[t];
    } else if (t < EE + NN) {
        int i = t - EE;
        size_t cell = (size_t)i * NN + i;
        if (g_win[cell] == 0) {              // no self-edge at (i,i)
            adj_lp[cell] = g_ilp[i] * g_ilp[i];
            adj_hp[cell] = 1.0f;
        }
    }
}

// Unnorm/mask scatter: duplicates write the same value. (Exposed tail — lean.)
__global__ void k_fin_unnorm(const int* __restrict__ edges, float* __restrict__ unnorm) {
    int t = blockIdx.x * blockDim.x + threadIdx.x;
    if (t >= EE) return;
    int u = edges[t], v = edges[EE + t];
    unnorm[(size_t)u * NN + v] = 1.0f;
}

extern "C" void kernel_launch(void* const* d_in, const int* in_sizes, int n_in,
                              void* d_out, int out_size) {
    const float* feat  = (const float*)d_in[0];
    const int*   edges = (const int*)  d_in[1];
    const float* wemb  = (const float*)d_in[2];
    const float* bemb  = (const float*)d_in[3];
    const float* wmlp  = (const float*)d_in[4];
    const float* bmlp  = (const float*)d_in[5];
    const float* gn    = (const float*)d_in[6];

    float* out     = (float*)d_out;
    float* adj_lp  = out;
    float* adj_hp  = out + (size_t)NN * NN;
    float* wlp     = out + 2ull * NN * NN;
    float* whp     = wlp + EE;
    float* unnorm  = whp + EE;

    static cudaStream_t s_f = nullptr, s_p = nullptr;
    static cudaEvent_t ev_fork = nullptr, ev_p = nullptr,
                       ev_adj = nullptr, ev_u = nullptr;
    if (!s_f) {
        cudaStreamCreateWithFlags(&s_f, cudaStreamNonBlocking);
        cudaStreamCreateWithFlags(&s_p, cudaStreamNonBlocking);
        cudaEventCreateWithFlags(&ev_fork, cudaEventDisableTiming);
        cudaEventCreateWithFlags(&ev_p,    cudaEventDisableTiming);
        cudaEventCreateWithFlags(&ev_adj,  cudaEventDisableTiming);
        cudaEventCreateWithFlags(&ev_u,    cudaEventDisableTiming);
    }

    const int TB = 256;
    const size_t MAT = (size_t)NN * NN;   // elements per matrix
    const int FG = 148 * 16;

    // Fork.
    cudaEventRecord(ev_fork, 0);
    cudaStreamWaitEvent(s_f, ev_fork, 0);
    cudaStreamWaitEvent(s_p, ev_fork, 0);

    // Fill stream: adjacency (288 MB, contiguous) FIRST so its scatter overlaps
    // the unnorm fill; unnorm (144 MB) second. Exposed tail = lean unnorm scatter.
    k_fill<<<FG, 512, 0, s_f>>>((float4*)adj_lp, (2ull * MAT) / 4);
    cudaEventRecord(ev_adj, s_f);
    k_fill<<<FG, 512, 0, s_f>>>((float4*)unnorm, MAT / 4);
    cudaEventRecord(ev_u, s_f);

    // p stream: node scalar projection.
    k_p<<<NN / NPB, HH, 0, s_p>>>(feat, wemb, bemb, wmlp);
    cudaEventRecord(ev_p, s_p);

    // Main chain (all hidden under the adj fill): winner bookkeeping, gating,
    // norms, and per-edge value precomputation.
    k_clear<<<(EE + TB - 1) / TB, TB>>>(edges);
    k_max  <<<(EE + TB - 1) / TB, TB>>>(edges);
    cudaStreamWaitEvent(0, ev_p, 0);
    k_edge<<<(EE + TB - 1) / TB, TB>>>(edges, gn, bmlp, wlp, whp);
    k_inv <<<(NN + TB - 1) / TB, TB>>>();
    k_vals<<<(EE + TB - 1) / TB, TB>>>(edges, wlp);

    // Adjacency scatter: starts when the adj fill lands; overlaps the unnorm fill.
    cudaStreamWaitEvent(0, ev_adj, 0);
    k_fin_adj<<<(EE + NN + TB - 1) / TB, TB>>>(edges, adj_lp, adj_hp);

    // Tail: lean unnorm scatter after the final fill.
    cudaStreamWaitEvent(0, ev_u, 0);
    k_fin_unnorm<<<(EE + TB - 1) / TB, TB>>>(edges, unnorm);
}

// round 11
// speedup vs baseline: 1.0585x; 1.0585x over previous
#include <cuda_runtime.h>
#include <math.h>

#define NN   6000
#define EE   192000
#define DIN  512
#define HH   128
#define NPB  8           // nodes per block in p-kernel
#define EOSF 1e-10f

// Scratch (__device__ globals allowed; heap allocs are not).
__device__ int   g_win[(size_t)NN * NN];   // winner edge-index+1 per cell (only edge cells touched)
__device__ float g_p[NN];
__device__ float g_dlp[NN];
__device__ float g_dhp[NN];
__device__ float g_ilp[NN];
__device__ float g_ihp[NN];
__device__ float g_vlp[EE];                // precomputed adj_lp value per edge (0 = not winner)
__device__ float g_vhp[EE];                // precomputed adj_hp value per edge
__device__ float g_diag_lp[NN];            // diagonal base values (0 = self-edge winner exists)
__device__ float g_diag_hp[NN];
__device__ int   g_diag_skip[NN];          // 1 = self-edge winner covers the diagonal

// SM-side zero fill (write-through float4 stores — best measured variant).
__global__ void __launch_bounds__(512) k_fill(float4* __restrict__ dst, size_t n4) {
    size_t i = (size_t)blockIdx.x * blockDim.x + threadIdx.x;
    size_t stride = (size_t)gridDim.x * blockDim.x;
    const float4 z = make_float4(0.f, 0.f, 0.f, 0.f);
    for (; i < n4; i += stride) __stwt(dst + i, z);
}

// Clear winner at all edge cells; init degrees to 1.0 (the +eye term in row sums).
__global__ void k_clear(const int* __restrict__ edges) {
    int t = blockIdx.x * blockDim.x + threadIdx.x;
    if (t < EE) {
        int u = edges[t], v = edges[EE + t];
        g_win[u * NN + v] = 0;
    }
    if (t < NN) { g_dlp[t] = 1.0f; g_dhp[t] = 1.0f; }
}

// Last-edge-wins dedup: winner = max edge index + 1.
__global__ void k_max(const int* __restrict__ edges) {
    int e = blockIdx.x * blockDim.x + threadIdx.x;
    if (e >= EE) return;
    int u = edges[e], v = edges[EE + e];
    atomicMax(&g_win[u * NN + v], e + 1);
}

// p[n] = sum_h relu(feat[n]·w_emb[:,h] + b_emb[h]) * (w_mlp[h] + w_mlp[H+h])
__global__ void __launch_bounds__(HH) k_p(const float* __restrict__ feat,
                                          const float* __restrict__ wemb,
                                          const float* __restrict__ bemb,
                                          const float* __restrict__ wmlp) {
    __shared__ float sf[NPB][DIN];
    int h  = threadIdx.x;
    int n0 = blockIdx.x * NPB;

    const float4* f4 = (const float4*)(feat + (size_t)n0 * DIN);
    float4* s4 = (float4*)&sf[0][0];
    const int total4 = NPB * DIN / 4;
    for (int i = h; i < total4; i += HH) s4[i] = f4[i];
    __syncthreads();

    float acc[NPB];
#pragma unroll
    for (int j = 0; j < NPB; j++) acc[j] = 0.0f;

    for (int d = 0; d < DIN; d += 4) {
        float w0 = wemb[(d + 0) * HH + h];
        float w1 = wemb[(d + 1) * HH + h];
        float w2 = wemb[(d + 2) * HH + h];
        float w3 = wemb[(d + 3) * HH + h];
#pragma unroll
        for (int j = 0; j < NPB; j++) {
            float4 f = *(const float4*)&sf[j][d];
            acc[j] = fmaf(f.x, w0, acc[j]);
            acc[j] = fmaf(f.y, w1, acc[j]);
            acc[j] = fmaf(f.z, w2, acc[j]);
            acc[j] = fmaf(f.w, w3, acc[j]);
        }
    }

    float b  = bemb[h];
    float ws = wmlp[h] + wmlp[HH + h];
    __shared__ float red[4][NPB];
#pragma unroll
    for (int j = 0; j < NPB; j++) {
        float v = acc[j] + b;
        v = (v > 0.0f) ? v * ws : 0.0f;
#pragma unroll
        for (int off = 16; off; off >>= 1) v += __shfl_down_sync(0xffffffffu, v, off);
        if ((h & 31) == 0) red[h >> 5][j] = v;
    }
    __syncthreads();
    if (h < NPB)
        g_p[n0 + h] = red[0][h] + red[1][h] + red[2][h] + red[3][h];
}

// Per-edge gating weights + winner-only degree accumulation (row sums).
__global__ void k_edge(const int* __restrict__ edges, const float* __restrict__ gn,
                       const float* __restrict__ bmlp,
                       float* __restrict__ wlp_out, float* __restrict__ whp_out) {
    int e = blockIdx.x * blockDim.x + threadIdx.x;
    if (e >= EE) return;
    int u = edges[e], v = edges[EE + e];
    float raw = 0.5f * (g_p[u] + g_p[v]) + bmlp[0];
    float x   = gn[e] + raw;               // TEMP = 1
    float wlp = 1.0f / (1.0f + expf(-x));
    wlp_out[e] = wlp;
    whp_out[e] = 1.0f - wlp;
    if (g_win[u * NN + v] == e + 1) {       // deduped adjacency contribution
        atomicAdd(&g_dlp[u], wlp);
        atomicAdd(&g_dhp[u], 1.0f - wlp);
    }
}

// Inverse norms + precomputed diagonal base values (self-edge check hidden here).
__global__ void k_inv() {
    int i = blockIdx.x * blockDim.x + threadIdx.x;
    if (i >= NN) return;
    float il = 1.0f / (sqrtf(g_dlp[i]) + EOSF);
    float ih = 1.0f / (sqrtf(g_dhp[i]) + EOSF);
    g_ilp[i] = il;
    g_ihp[i] = ih;
    int skip = (g_win[(size_t)i * NN + i] != 0);  // self-edge winner covers diag
    g_diag_skip[i] = skip;
    g_diag_lp[i] = il * il;
    g_diag_hp[i] = 1.0f;
}

// Precompute per-edge scatter values (hidden under the fill window).
// vlp == 0 marks non-winner edges (winner values are strictly positive).
__global__ void k_vals(const int* __restrict__ edges, const float* __restrict__ wlp_out) {
    int e = blockIdx.x * blockDim.x + threadIdx.x;
    if (e >= EE) return;
    int u = edges[e], v = edges[EE + e];
    size_t cell = (size_t)u * NN + v;
    float vlp = 0.0f, vhp = 0.0f;
    if (g_win[cell] == e + 1) {
        float wlp = wlp_out[e];
        float il = g_ilp[u] * g_ilp[v];
        float ih = g_ihp[u] * g_ihp[v];
        if (u == v) {
            vlp = (1.0f + wlp) * il;             // eye + self-edge, normalized
            vhp = 1.0f - (2.0f - wlp) * ih;      // 1 - (whp + 1)*ih
        } else {
            vlp = wlp * il;
            vhp = -(1.0f - wlp) * ih;
        }
    }
    g_vlp[e] = vlp;
    g_vhp[e] = vhp;
}

// Unnorm/mask scatter: duplicates write the same value. Overlaps the adj fill
// (this overlap was present in the best round and is benign).
__global__ void k_fin_unnorm(const int* __restrict__ edges, float* __restrict__ unnorm) {
    int t = blockIdx.x * blockDim.x + threadIdx.x;
    if (t >= EE) return;
    int u = edges[t], v = edges[EE + t];
    unnorm[(size_t)u * NN + v] = 1.0f;
}

// Lean adjacency tail: all values precomputed; no winner-matrix reads, no FP math.
__global__ void k_fin_adj(const int* __restrict__ edges,
                          float* __restrict__ adj_lp, float* __restrict__ adj_hp) {
    int t = blockIdx.x * blockDim.x + threadIdx.x;
    if (t < EE) {
        float vlp = g_vlp[t];
        if (vlp == 0.0f) return;
        int u = edges[t], v = edges[EE + t];
        size_t cell = (size_t)u * NN + v;
        adj_lp[cell] = vlp;
        adj_hp[cell] = g_vhp[t];
    } else if (t < EE + NN) {
        int i = t - EE;
        if (g_diag_skip[i]) return;
        size_t cell = (size_t)i * NN + i;
        adj_lp[cell] = g_diag_lp[i];
        adj_hp[cell] = g_diag_hp[i];
    }
}

extern "C" void kernel_launch(void* const* d_in, const int* in_sizes, int n_in,
                              void* d_out, int out_size) {
    const float* feat  = (const float*)d_in[0];
    const int*   edges = (const int*)  d_in[1];
    const float* wemb  = (const float*)d_in[2];
    const float* bemb  = (const float*)d_in[3];
    const float* wmlp  = (const float*)d_in[4];
    const float* bmlp  = (const float*)d_in[5];
    const float* gn    = (const float*)d_in[6];

    float* out     = (float*)d_out;
    float* adj_lp  = out;
    float* adj_hp  = out + (size_t)NN * NN;
    float* wlp     = out + 2ull * NN * NN;
    float* whp     = wlp + EE;
    float* unnorm  = whp + EE;

    static cudaStream_t s_f = nullptr, s_p = nullptr;
    static cudaEvent_t ev_fork = nullptr, ev_p = nullptr, ev_un = nullptr,
                       ev_u = nullptr, ev_adj = nullptr;
    if (!s_f) {
        cudaStreamCreateWithFlags(&s_f, cudaStreamNonBlocking);
        cudaStreamCreateWithFlags(&s_p, cudaStreamNonBlocking);
        cudaEventCreateWithFlags(&ev_fork, cudaEventDisableTiming);
        cudaEventCreateWithFlags(&ev_p,    cudaEventDisableTiming);
        cudaEventCreateWithFlags(&ev_un,   cudaEventDisableTiming);
        cudaEventCreateWithFlags(&ev_u,    cudaEventDisableTiming);
        cudaEventCreateWithFlags(&ev_adj,  cudaEventDisableTiming);
    }

    const int TB = 256;
    const size_t MAT = (size_t)NN * NN;   // elements per matrix
    const int FG = 148 * 16;

    // Fork.
    cudaEventRecord(ev_fork, 0);
    cudaStreamWaitEvent(s_f, ev_fork, 0);
    cudaStreamWaitEvent(s_p, ev_fork, 0);

    // Fill stream (R6 order): unnorm first, adjacency (288 MB contiguous) second.
    k_fill<<<FG, 512, 0, s_f>>>((float4*)unnorm, MAT / 4);
    cudaEventRecord(ev_u, s_f);
    k_fill<<<FG, 512, 0, s_f>>>((float4*)adj_lp, (2ull * MAT) / 4);
    cudaEventRecord(ev_adj, s_f);

    // p stream: node scalar projection, then unnorm scatter once its fill lands.
    k_p<<<NN / NPB, HH, 0, s_p>>>(feat, wemb, bemb, wmlp);
    cudaEventRecord(ev_p, s_p);
    cudaStreamWaitEvent(s_p, ev_u, 0);
    k_fin_unnorm<<<(EE + TB - 1) / TB, TB, 0, s_p>>>(edges, unnorm);
    cudaEventRecord(ev_un, s_p);

    // Main chain (hidden under the fills): winner bookkeeping, gating, norms,
    // diagonal + per-edge value precomputation.
    k_clear<<<(EE + TB - 1) / TB, TB>>>(edges);
    k_max  <<<(EE + TB - 1) / TB, TB>>>(edges);
    cudaStreamWaitEvent(0, ev_p, 0);
    k_edge<<<(EE + TB - 1) / TB, TB>>>(edges, gn, bmlp, wlp, whp);
    k_inv <<<(NN + TB - 1) / TB, TB>>>();
    k_vals<<<(EE + TB - 1) / TB, TB>>>(edges, wlp);

    // Lean tail: starts only after ALL fills have drained (overlap regresses).
    cudaStreamWaitEvent(0, ev_adj, 0);
    k_fin_adj<<<(EE + NN + TB - 1) / TB, TB>>>(edges, adj_lp, adj_hp);

    // Join the unnorm branch so the graph has a single terminal.
    cudaStreamWaitEvent(0, ev_un, 0);
}